// round 13
// baseline (speedup 1.0000x reference)
#include <cuda_runtime.h>
#include <cuda_bf16.h>
#include <cstdint>
#include <math.h>

#define NEGV 1000000000000.0f

// ---------------- scratch (static device globals; no allocs) ----------------
__device__ float g_qT[4 * 64 * 1024];    // rope'd q, TRANSPOSED [b][d][m], pre-scaled 1/8
__device__ float g_kT[4 * 64 * 1024];    // rope'd k, TRANSPOSED [b][d][n]
__device__ float g_bA[4 * 16 * 1024];    // bias[b, n, 2o]/2   -> indexed [b][o][n]
__device__ float g_bB[4 * 16 * 1024];    // bias[b, m, 2o+1]/2 -> indexed [b][o][m]

// ---------------- packed f32x2 helpers ----------------
__device__ __forceinline__ unsigned long long pk2(float lo, float hi) {
    unsigned long long r;
    asm("mov.b64 %0, {%1,%2};" : "=l"(r) : "f"(lo), "f"(hi));
    return r;
}
__device__ __forceinline__ void fma2(unsigned long long& d, unsigned long long a,
                                     unsigned long long b) {
    asm("fma.rn.f32x2 %0, %1, %2, %0;" : "+l"(d) : "l"(a), "l"(b));
}
__device__ __forceinline__ unsigned long long fma2n(unsigned long long a,
                                                    unsigned long long b,
                                                    unsigned long long c) {
    unsigned long long d;
    asm("fma.rn.f32x2 %0, %1, %2, %3;" : "=l"(d) : "l"(a), "l"(b), "l"(c));
    return d;
}
__device__ __forceinline__ unsigned long long add2(unsigned long long a,
                                                   unsigned long long b) {
    unsigned long long d;
    asm("add.rn.f32x2 %0, %1, %2;" : "=l"(d) : "l"(a), "l"(b));
    return d;
}
__device__ __forceinline__ float2 up2(unsigned long long v) {
    float2 r;
    asm("mov.b64 {%0,%1}, %2;" : "=f"(r.x), "=f"(r.y) : "l"(v));
    return r;
}
__device__ __forceinline__ uint32_t packbf2(float a, float b) {
    __nv_bfloat162 v = __floats2bfloat162_rn(a, b);
    return *(uint32_t*)&v;
}
__device__ __forceinline__ void ldsm_x4(uint32_t& r0, uint32_t& r1, uint32_t& r2,
                                        uint32_t& r3, uint32_t addr) {
    asm volatile("ldmatrix.sync.aligned.m8n8.x4.shared.b16 {%0,%1,%2,%3}, [%4];"
                 : "=r"(r0), "=r"(r1), "=r"(r2), "=r"(r3) : "r"(addr));
}
__device__ __forceinline__ void ldsm_x4t(uint32_t& r0, uint32_t& r1, uint32_t& r2,
                                         uint32_t& r3, uint32_t addr) {
    asm volatile("ldmatrix.sync.aligned.m8n8.x4.trans.shared.b16 {%0,%1,%2,%3}, [%4];"
                 : "=r"(r0), "=r"(r1), "=r"(r2), "=r"(r3) : "r"(addr));
}
__device__ __forceinline__ void mma_bf16(float* d, uint32_t a0, uint32_t a1,
                                         uint32_t a2, uint32_t a3, uint32_t b0,
                                         uint32_t b1) {
    asm volatile(
        "mma.sync.aligned.m16n8k16.row.col.f32.bf16.bf16.f32 "
        "{%0,%1,%2,%3}, {%4,%5,%6,%7}, {%8,%9}, {%0,%1,%2,%3};"
        : "+f"(d[0]), "+f"(d[1]), "+f"(d[2]), "+f"(d[3])
        : "r"(a0), "r"(a1), "r"(a2), "r"(a3), "r"(b0), "r"(b1));
}

// ---------------- kernel 1 (fused, BM=64): h=x@W1+b1 -> RoPE + bias ---------
// 64 blocks (64 rows each), 256 thr (8 warps). K=768 in 12 double-buffered
// BK=64 stages, W1 converted fp32->bf16 inline. Warp: mw=warp&3 (m16 tile),
// nv=warp>>2 (n64 half). smem (dynamic, 53888B):
//   A bufs @0 (2x8KB), B bufs @16384 (2x16KB), b1s @53248, invf @53760.
//   epilogue: h_s (64x133) @0, rq_s [64][36] @34816, rk_s @44032.
__global__ __launch_bounds__(256) void k1_kernel(
    const float* __restrict__ x, const float* __restrict__ W1,
    const float* __restrict__ b1, const float* __restrict__ W2,
    const float* __restrict__ b2) {
    extern __shared__ __align__(16) unsigned char smem[];
    const uint32_t sbase = (uint32_t)__cvta_generic_to_shared(smem);
    float* b1s = (float*)(smem + 53248);
    float* invf_s = (float*)(smem + 53760);

    const int tid = threadIdx.x;
    const int lane = tid & 31;
    const int warp = tid >> 5;
    const int row0 = blockIdx.x * 64;

    if (tid < 128) b1s[tid] = b1[tid];
    else if (tid < 160) {
        int j = tid - 128;
        invf_s[j] = (float)exp(-(double)j * (9.210340371976184 / 32.0));
    }

    // A staging: thread -> 2 consecutive 16B bf16 chunks of one row
    const int As_row = tid >> 2;            // 0..63
    const int As_c0 = (tid & 3) * 2;        // chunk 0..7 (pairs)
    const int As_csw0 = (As_c0 ^ (As_row & 7)) & 7;
    const int As_csw1 = ((As_c0 + 1) ^ (As_row & 7)) & 7;
    const float* xr = x + (size_t)(row0 + As_row) * 768 + As_c0 * 8;

    // B staging: thread -> 4 bf16 chunks per stage (from fp32 W1)
    int Bs_row[4], Bs_nc[4], Bs_csw[4];
#pragma unroll
    for (int i = 0; i < 4; i++) {
        int c = tid + 256 * i;
        Bs_row[i] = c >> 4;
        Bs_nc[i] = c & 15;
        Bs_csw[i] = (Bs_nc[i] & 8) | ((Bs_nc[i] ^ Bs_row[i]) & 7);
    }

    float4 pA[4], pB0[4], pB1[4];

    // ---- prologue: load + stage kt=0 ----
    {
#pragma unroll
        for (int i = 0; i < 4; i++) {
            const float* src = W1 + (size_t)Bs_row[i] * 128 + Bs_nc[i] * 8;
            pB0[i] = *(const float4*)src;
            pB1[i] = *(const float4*)(src + 4);
        }
        pA[0] = *(const float4*)xr;       pA[1] = *(const float4*)(xr + 4);
        pA[2] = *(const float4*)(xr + 8); pA[3] = *(const float4*)(xr + 12);
#pragma unroll
        for (int i = 0; i < 4; i++) {
            uint4 p;
            p.x = packbf2(pB0[i].x, pB0[i].y); p.y = packbf2(pB0[i].z, pB0[i].w);
            p.z = packbf2(pB1[i].x, pB1[i].y); p.w = packbf2(pB1[i].z, pB1[i].w);
            *(uint4*)(smem + 16384 + Bs_row[i] * 256 + Bs_csw[i] * 16) = p;
        }
        {
            uint4 p;
            p.x = packbf2(pA[0].x, pA[0].y); p.y = packbf2(pA[0].z, pA[0].w);
            p.z = packbf2(pA[1].x, pA[1].y); p.w = packbf2(pA[1].z, pA[1].w);
            *(uint4*)(smem + As_row * 128 + As_csw0 * 16) = p;
            p.x = packbf2(pA[2].x, pA[2].y); p.y = packbf2(pA[2].z, pA[2].w);
            p.z = packbf2(pA[3].x, pA[3].y); p.w = packbf2(pA[3].z, pA[3].w);
            *(uint4*)(smem + As_row * 128 + As_csw1 * 16) = p;
        }
        __syncthreads();
    }

    const int mw = warp & 3;            // m16 tile (0..3)
    const int nv = warp >> 2;           // n64 half (0..1)
    const int arow = mw * 16 + (lane & 15);
    const int ar7 = arow & 7;
    const int brow16 = lane & 15;
    const int bhi = lane >> 4;

    float d[8][4];
#pragma unroll
    for (int t = 0; t < 8; t++)
#pragma unroll
        for (int j = 0; j < 4; j++) d[t][j] = 0.0f;

    for (int kt = 0; kt < 12; kt++) {
        const uint32_t abuf = (kt & 1) * 8192;
        const uint32_t bbuf = 16384 + (kt & 1) * 16384;

        if (kt < 11) {
            const float* wb = W1 + (size_t)(kt + 1) * 64 * 128;
#pragma unroll
            for (int i = 0; i < 4; i++) {
                const float* src = wb + (size_t)Bs_row[i] * 128 + Bs_nc[i] * 8;
                pB0[i] = *(const float4*)src;
                pB1[i] = *(const float4*)(src + 4);
            }
            const float* xs = xr + (kt + 1) * 64;
            pA[0] = *(const float4*)xs;       pA[1] = *(const float4*)(xs + 4);
            pA[2] = *(const float4*)(xs + 8); pA[3] = *(const float4*)(xs + 12);
        }

        // compute kt: 4 k16-steps, each 1 ldsm A + 4 ldsm.t B + 8 HMMA
#pragma unroll
        for (int ks = 0; ks < 4; ks++) {
            uint32_t a0, a1, a2, a3;
            {
                int chunk = ks * 2 + bhi;
                int csw = (chunk ^ ar7) & 7;
                ldsm_x4(a0, a1, a2, a3, sbase + abuf + arow * 128 + csw * 16);
            }
            int brow = ks * 16 + brow16;
            uint32_t braddr = sbase + bbuf + brow * 256;
            int br7 = brow & 7;
#pragma unroll
            for (int ntp = 0; ntp < 4; ntp++) {
                uint32_t b0, b1r, b2, b3;
                int chunk = nv * 8 + ntp * 2 + bhi;
                int csw = (chunk & 8) | ((chunk ^ br7) & 7);
                ldsm_x4t(b0, b1r, b2, b3, braddr + csw * 16);
                mma_bf16(d[2 * ntp],     a0, a1, a2, a3, b0, b1r);
                mma_bf16(d[2 * ntp + 1], a0, a1, a2, a3, b2, b3);
            }
        }

        if (kt < 11) {
            unsigned char* bd = smem + 16384 + (((kt + 1) & 1)) * 16384;
#pragma unroll
            for (int i = 0; i < 4; i++) {
                uint4 p;
                p.x = packbf2(pB0[i].x, pB0[i].y); p.y = packbf2(pB0[i].z, pB0[i].w);
                p.z = packbf2(pB1[i].x, pB1[i].y); p.w = packbf2(pB1[i].z, pB1[i].w);
                *(uint4*)(bd + Bs_row[i] * 256 + Bs_csw[i] * 16) = p;
            }
            unsigned char* ad = smem + (((kt + 1) & 1) * 8192);
            uint4 p;
            p.x = packbf2(pA[0].x, pA[0].y); p.y = packbf2(pA[0].z, pA[0].w);
            p.z = packbf2(pA[1].x, pA[1].y); p.w = packbf2(pA[1].z, pA[1].w);
            *(uint4*)(ad + As_row * 128 + As_csw0 * 16) = p;
            p.x = packbf2(pA[2].x, pA[2].y); p.y = packbf2(pA[2].z, pA[2].w);
            p.z = packbf2(pA[3].x, pA[3].y); p.w = packbf2(pA[3].z, pA[3].w);
            *(uint4*)(ad + As_row * 128 + As_csw1 * 16) = p;
            __syncthreads();
        }
    }
    __syncthreads();   // all warps done with A/B smem

    // ---- acc(+b1) -> h tile in smem ----
    float* h_s = (float*)smem;                    // 64 x 133 (34048 B)
    float* rq_s = (float*)(smem + 34816);         // [64][36]  (9216 B)
    float* rk_s = (float*)(smem + 44032);         // [64][36]  (9216 B)
    {
        int r = mw * 16 + (lane >> 2);
#pragma unroll
        for (int nt = 0; nt < 8; nt++) {
            int col = nv * 64 + nt * 8 + 2 * (lane & 3);
            h_s[r * 133 + col]           = d[nt][0] + b1s[col];
            h_s[r * 133 + col + 1]       = d[nt][1] + b1s[col + 1];
            h_s[(r + 8) * 133 + col]     = d[nt][2] + b1s[col];
            h_s[(r + 8) * 133 + col + 1] = d[nt][3] + b1s[col + 1];
        }
    }
    __syncthreads();

    const int tn = tid & 31;
    const int tmw = tid >> 5;
    const int b = row0 >> 10;
    const int s0 = row0 & 1023;
    const float invfe = invf_s[(2 * tn) & 31];
    const float invfo = invf_s[(2 * tn + 1) & 31];

    // ---- RoPE + coalesced writeback, two passes of 32 rows ----
#pragma unroll
    for (int p = 0; p < 2; p++) {
#pragma unroll
        for (int mi = 0; mi < 4; mi++) {
            int r = 4 * tmw + mi;
            int rr = p * 32 + r;
            float h0 = h_s[rr * 133 + 4 * tn + 0];
            float h1 = h_s[rr * 133 + 4 * tn + 1];
            float h2 = h_s[rr * 133 + 4 * tn + 2];
            float h3 = h_s[rr * 133 + 4 * tn + 3];

            float fs = (float)(s0 + rr);
            float se, ce, so, co;
            sincosf(fs * invfe, &se, &ce);
            sincosf(fs * invfo, &so, &co);

            rq_s[(2 * tn) * 36 + r]     = (h0 * ce - h2 * se) * 0.125f;
            rq_s[(2 * tn + 1) * 36 + r] = (h2 * co + h0 * so) * 0.125f;
            rk_s[(2 * tn) * 36 + r]     = h1 * ce - h3 * se;
            rk_s[(2 * tn + 1) * 36 + r] = h3 * co + h1 * so;
        }
        __syncthreads();
        {
            int dd = tid >> 2, ch = tid & 3;
            int scol = s0 + p * 32 + ch * 8;
            float4 v0 = *(const float4*)&rq_s[dd * 36 + ch * 8];
            float4 v1 = *(const float4*)&rq_s[dd * 36 + ch * 8 + 4];
            float* dst = g_qT + (size_t)(b * 64 + dd) * 1024 + scol;
            *(float4*)dst = v0;
            *(float4*)(dst + 4) = v1;
            float4 w0 = *(const float4*)&rk_s[dd * 36 + ch * 8];
            float4 w1 = *(const float4*)&rk_s[dd * 36 + ch * 8 + 4];
            float* dstk = g_kT + (size_t)(b * 64 + dd) * 1024 + scol;
            *(float4*)dstk = w0;
            *(float4*)(dstk + 4) = w1;
        }
        __syncthreads();
    }

    // ---- bias GEMM: h @ W2 + b2 (thread -> 1 row x 8 out channels) ----
    {
        const int r = tid & 63;
        const int hbase = (tid >> 6) * 8;
        float4 acc0 = *(const float4*)(b2 + hbase);
        float4 acc1 = *(const float4*)(b2 + hbase + 4);
        const float* hp = h_s + r * 133;
#pragma unroll 8
        for (int kk = 0; kk < 128; kk++) {
            float hv = hp[kk];
            float4 w0 = *(const float4*)(W2 + kk * 32 + hbase);
            float4 w1 = *(const float4*)(W2 + kk * 32 + hbase + 4);
            acc0.x += hv * w0.x; acc0.y += hv * w0.y;
            acc0.z += hv * w0.z; acc0.w += hv * w0.w;
            acc1.x += hv * w1.x; acc1.y += hv * w1.y;
            acc1.z += hv * w1.z; acc1.w += hv * w1.w;
        }
        int s = s0 + r;
        float vals[8] = {acc0.x * 0.5f, acc0.y * 0.5f, acc0.z * 0.5f, acc0.w * 0.5f,
                         acc1.x * 0.5f, acc1.y * 0.5f, acc1.z * 0.5f, acc1.w * 0.5f};
#pragma unroll
        for (int j = 0; j < 8; j++) {
            int ho = hbase + j;
            int o = ho >> 1;
            if (ho & 1) g_bB[(size_t)(b * 16 + o) * 1024 + s] = vals[j];
            else        g_bA[(size_t)(b * 16 + o) * 1024 + s] = vals[j];
        }
    }
}

// ---------------- kernel 2: logits (best known, ~45.5us) ----------------
__global__ __launch_bounds__(256) void k2_kernel(const float* __restrict__ mask,
                                                 float* __restrict__ out) {
    __shared__ __align__(16) float q_s[64 * 32];    // [k][m]   8KB
    __shared__ __align__(16) float k_s[64 * 128];   // [k][n]  32KB
    __shared__ __align__(16) float bA_s[16 * 128];  // [o][n]   8KB
    __shared__ __align__(16) float bB_s[16 * 32];   // [o][m]   2KB

    const int tid = threadIdx.x;
    const int tn = tid & 31;
    const int tm = tid >> 5;
    const int b = blockIdx.z;
    const int m0 = blockIdx.y * 32;
    const int n0 = blockIdx.x * 128;

    {
        const float* src = g_qT + (size_t)b * 65536 + m0;
#pragma unroll
        for (int i = 0; i < 2; i++) {
            int f = tid + 256 * i;
            int kk = f >> 3, col = (f & 7) * 4;
            *(float4*)&q_s[kk * 32 + col] = *(const float4*)(src + kk * 1024 + col);
        }
    }
    {
        const float* src = g_kT + (size_t)b * 65536 + n0;
#pragma unroll
        for (int i = 0; i < 8; i++) {
            int f = tid + 256 * i;
            int kk = f >> 5, col = (f & 31) * 4;
            *(float4*)&k_s[kk * 128 + col] = *(const float4*)(src + kk * 1024 + col);
        }
    }
    {
        const float* bAg = g_bA + (size_t)(b * 16) * 1024 + n0;
#pragma unroll
        for (int i = 0; i < 2; i++) {
            int f = tid + 256 * i;
            int o = f >> 5, col = (f & 31) * 4;
            *(float4*)&bA_s[o * 128 + col] = *(const float4*)(bAg + o * 1024 + col);
        }
        if (tid < 128) {
            const float* bBg = g_bB + (size_t)(b * 16) * 1024 + m0;
            int o = tid >> 3, col = (tid & 7) * 4;
            *(float4*)&bB_s[o * 32 + col] = *(const float4*)(bBg + o * 1024 + col);
        }
    }
    __syncthreads();

    unsigned long long acc2[4][2];
#pragma unroll
    for (int mi = 0; mi < 4; mi++) { acc2[mi][0] = 0ULL; acc2[mi][1] = 0ULL; }

#pragma unroll 16
    for (int kk = 0; kk < 64; kk++) {
        float4 av = *(const float4*)&q_s[kk * 32 + 4 * tm];
        ulonglong2 bv = *(const ulonglong2*)&k_s[kk * 128 + 4 * tn];
        unsigned long long am;
        am = pk2(av.x, av.x); fma2(acc2[0][0], am, bv.x); fma2(acc2[0][1], am, bv.y);
        am = pk2(av.y, av.y); fma2(acc2[1][0], am, bv.x); fma2(acc2[1][1], am, bv.y);
        am = pk2(av.z, av.z); fma2(acc2[2][0], am, bv.x); fma2(acc2[2][1], am, bv.y);
        am = pk2(av.w, av.w); fma2(acc2[3][0], am, bv.x); fma2(acc2[3][1], am, bv.y);
    }

    const int nbase = n0 + 4 * tn;
    const int mbase = m0 + 4 * tm;

    float pm[4];
    {
        float4 mv = *(const float4*)(mask + b * 1024 + nbase);
        pm[0] = mv.x; pm[1] = mv.y; pm[2] = mv.z; pm[3] = mv.w;
    }
    unsigned long long pm2[2] = {pk2(pm[0], pm[1]), pk2(pm[2], pm[3])};

    unsigned long long dpm2[4][2];
#pragma unroll
    for (int mi = 0; mi < 4; mi++) {
        float2 u0 = up2(acc2[mi][0]);
        float2 u1 = up2(acc2[mi][1]);
        int mg = mbase + mi;
        float c0 = -(1.0f - pm[0]) * NEGV - (mg > nbase + 0 ? NEGV : 0.0f);
        float c1 = -(1.0f - pm[1]) * NEGV - (mg > nbase + 1 ? NEGV : 0.0f);
        float c2 = -(1.0f - pm[2]) * NEGV - (mg > nbase + 2 ? NEGV : 0.0f);
        float c3 = -(1.0f - pm[3]) * NEGV - (mg > nbase + 3 ? NEGV : 0.0f);
        dpm2[mi][0] = pk2(fmaf(u0.x, pm[0], c0), fmaf(u0.y, pm[1], c1));
        dpm2[mi][1] = pk2(fmaf(u1.x, pm[2], c2), fmaf(u1.y, pm[3], c3));
    }

    float* op0 = out + ((size_t)(b * 16) * 1024 + mbase) * 1024 + nbase;

#pragma unroll 4
    for (int o = 0; o < 16; o++) {
        float4 ba = *(const float4*)&bA_s[o * 128 + 4 * tn];
        float4 bb = *(const float4*)&bB_s[o * 32 + 4 * tm];
        unsigned long long ba2[2] = {pk2(ba.x, ba.y), pk2(ba.z, ba.w)};
        float bbv[4] = {bb.x, bb.y, bb.z, bb.w};
        float* op = op0 + (size_t)o * 1024 * 1024;
#pragma unroll
        for (int mi = 0; mi < 4; mi++) {
            unsigned long long bb2 = pk2(bbv[mi], bbv[mi]);
            unsigned long long v0 = fma2n(add2(ba2[0], bb2), pm2[0], dpm2[mi][0]);
            unsigned long long v1 = fma2n(add2(ba2[1], bb2), pm2[1], dpm2[mi][1]);
            float2 r0 = up2(v0);
            float2 r1 = up2(v1);
            float4 r = make_float4(r0.x, r0.y, r1.x, r1.y);
            __stcs((float4*)(op + (size_t)mi * 1024), r);
        }
    }
}

extern "C" void kernel_launch(void* const* d_in, const int* in_sizes, int n_in,
                              void* d_out, int out_size) {
    const float* x    = (const float*)d_in[0];  // (4,1024,768)
    const float* mask = (const float*)d_in[1];  // (4,1024)
    const float* W1   = (const float*)d_in[2];  // (768,128)
    const float* b1   = (const float*)d_in[3];  // (128)
    const float* W2   = (const float*)d_in[4];  // (128,32)
    const float* b2   = (const float*)d_in[5];  // (32)
    float* out = (float*)d_out;                 // (4,16,1024,1024)

    cudaFuncSetAttribute(k1_kernel, cudaFuncAttributeMaxDynamicSharedMemorySize,
                         53888);
    k1_kernel<<<64, 256, 53888>>>(x, W1, b1, W2, b2);
    k2_kernel<<<dim3(8, 32, 4), 256>>>(mask, out);
}

// round 14
// speedup vs baseline: 1.1055x; 1.1055x over previous
#include <cuda_runtime.h>
#include <cuda_bf16.h>
#include <cstdint>
#include <math.h>

#define NEGV 1000000000000.0f

// ---------------- scratch (static device globals; no allocs) ----------------
__device__ __align__(16) unsigned char g_w1b[768 * 128 * 2];  // W1 bf16 row-major
__device__ float g_qT[4 * 64 * 1024];    // rope'd q, TRANSPOSED [b][d][m], pre-scaled 1/8
__device__ float g_kT[4 * 64 * 1024];    // rope'd k, TRANSPOSED [b][d][n]
__device__ float g_bA[4 * 16 * 1024];    // bias[b, n, 2o]/2   -> indexed [b][o][n]
__device__ float g_bB[4 * 16 * 1024];    // bias[b, m, 2o+1]/2 -> indexed [b][o][m]

// ---------------- packed f32x2 helpers ----------------
__device__ __forceinline__ unsigned long long pk2(float lo, float hi) {
    unsigned long long r;
    asm("mov.b64 %0, {%1,%2};" : "=l"(r) : "f"(lo), "f"(hi));
    return r;
}
__device__ __forceinline__ void fma2(unsigned long long& d, unsigned long long a,
                                     unsigned long long b) {
    asm("fma.rn.f32x2 %0, %1, %2, %0;" : "+l"(d) : "l"(a), "l"(b));
}
__device__ __forceinline__ unsigned long long fma2n(unsigned long long a,
                                                    unsigned long long b,
                                                    unsigned long long c) {
    unsigned long long d;
    asm("fma.rn.f32x2 %0, %1, %2, %3;" : "=l"(d) : "l"(a), "l"(b), "l"(c));
    return d;
}
__device__ __forceinline__ unsigned long long add2(unsigned long long a,
                                                   unsigned long long b) {
    unsigned long long d;
    asm("add.rn.f32x2 %0, %1, %2;" : "=l"(d) : "l"(a), "l"(b));
    return d;
}
__device__ __forceinline__ float2 up2(unsigned long long v) {
    float2 r;
    asm("mov.b64 {%0,%1}, %2;" : "=f"(r.x), "=f"(r.y) : "l"(v));
    return r;
}
__device__ __forceinline__ void cp_async16(void* smem_dst, const void* gsrc) {
    unsigned saddr = (unsigned)__cvta_generic_to_shared(smem_dst);
    asm volatile("cp.async.ca.shared.global [%0], [%1], 16;\n"
                 :: "r"(saddr), "l"(gsrc) : "memory");
}
__device__ __forceinline__ uint32_t packbf2(float a, float b) {
    __nv_bfloat162 v = __floats2bfloat162_rn(a, b);
    return *(uint32_t*)&v;
}
__device__ __forceinline__ void ldsm_x4(uint32_t& r0, uint32_t& r1, uint32_t& r2,
                                        uint32_t& r3, uint32_t addr) {
    asm volatile("ldmatrix.sync.aligned.m8n8.x4.shared.b16 {%0,%1,%2,%3}, [%4];"
                 : "=r"(r0), "=r"(r1), "=r"(r2), "=r"(r3) : "r"(addr));
}
__device__ __forceinline__ void ldsm_x4t(uint32_t& r0, uint32_t& r1, uint32_t& r2,
                                         uint32_t& r3, uint32_t addr) {
    asm volatile("ldmatrix.sync.aligned.m8n8.x4.trans.shared.b16 {%0,%1,%2,%3}, [%4];"
                 : "=r"(r0), "=r"(r1), "=r"(r2), "=r"(r3) : "r"(addr));
}
__device__ __forceinline__ void mma_bf16(float* d, uint32_t a0, uint32_t a1,
                                         uint32_t a2, uint32_t a3, uint32_t b0,
                                         uint32_t b1) {
    asm volatile(
        "mma.sync.aligned.m16n8k16.row.col.f32.bf16.bf16.f32 "
        "{%0,%1,%2,%3}, {%4,%5,%6,%7}, {%8,%9}, {%0,%1,%2,%3};"
        : "+f"(d[0]), "+f"(d[1]), "+f"(d[2]), "+f"(d[3])
        : "r"(a0), "r"(a1), "r"(a2), "r"(a3), "r"(b0), "r"(b1));
}

// ---------------- prep: W1 -> bf16 row-major ----------------
__global__ __launch_bounds__(256) void prep_w1_kernel(const float* __restrict__ W1) {
    int i = (blockIdx.x * 256 + threadIdx.x) * 4;   // 98304 elements
    float4 v = *(const float4*)(W1 + i);
    uint2 p;
    p.x = packbf2(v.x, v.y);
    p.y = packbf2(v.z, v.w);
    *(uint2*)(g_w1b + (size_t)i * 2) = p;
}

// ---------------- kernel 1 (fused): h = x@W1+b1 -> RoPE qT/kT + bias --------
// 128 blocks (32 rows), 256 thr (8 warps). Full K=768 in 12 double-buffered
// BK=64 stages; B via cp.async from g_w1b, A via LDG->bf16-pack->STS.
// smem: A bufs @0 (2x4KB), B bufs @8192 (2x16KB), b1s @40960, invf @41472.
// epilogue reuse: h_s (32x133) @0, rq_s [64][36] @17408, rk_s @26624.
__global__ __launch_bounds__(256) void k1_kernel(
    const float* __restrict__ x, const float* __restrict__ b1,
    const float* __restrict__ W2, const float* __restrict__ b2) {
    __shared__ __align__(16) unsigned char smem[41600];
    const uint32_t sbase = (uint32_t)__cvta_generic_to_shared(smem);
    float* b1s = (float*)(smem + 40960);
    float* invf_s = (float*)(smem + 41472);

    const int tid = threadIdx.x;
    const int lane = tid & 31;
    const int warp = tid >> 5;
    const int row0 = blockIdx.x * 32;

    if (tid < 128) b1s[tid] = b1[tid];
    else if (tid < 160) {
        int j = tid - 128;
        invf_s[j] = (float)exp(-(double)j * (9.210340371976184 / 32.0));
    }

    // A staging map: thread -> one 16B chunk (8 bf16) of the 32x64 tile
    const int As_row = tid >> 3;       // 0..31
    const int As_kc = tid & 7;         // 0..7
    const int As_csw = (As_kc ^ (As_row & 7)) & 7;
    const float* xr = x + (size_t)(row0 + As_row) * 768 + As_kc * 8;

    // ---- prologue: stage kt=0 ----
    {
#pragma unroll
        for (int i = 0; i < 4; i++) {
            int c = tid + 256 * i;             // 1024 chunks
            int row = c >> 4, nc = c & 15;
            int csw = (nc & 8) | ((nc ^ row) & 7);
            cp_async16(smem + 8192 + row * 256 + csw * 16,
                       g_w1b + (size_t)row * 256 + nc * 16);
        }
        asm volatile("cp.async.commit_group;" ::: "memory");
        float4 v0 = *(const float4*)xr;
        float4 v1 = *(const float4*)(xr + 4);
        uint4 p;
        p.x = packbf2(v0.x, v0.y); p.y = packbf2(v0.z, v0.w);
        p.z = packbf2(v1.x, v1.y); p.w = packbf2(v1.z, v1.w);
        *(uint4*)(smem + As_row * 128 + As_csw * 16) = p;
        asm volatile("cp.async.wait_group 0;" ::: "memory");
        __syncthreads();
    }

    const int mw = warp & 1;           // m16 tile
    const int nv = warp >> 1;          // n32 group (0..3)
    const int arow = mw * 16 + (lane & 15);
    const int ar7 = arow & 7;
    const int brow16 = lane & 15;
    const int bhi = lane >> 4;

    float d[4][4];
#pragma unroll
    for (int t = 0; t < 4; t++)
#pragma unroll
        for (int j = 0; j < 4; j++) d[t][j] = 0.0f;

    float4 pv0, pv1;
    for (int kt = 0; kt < 12; kt++) {
        const uint32_t abuf = (kt & 1) * 4096;
        const uint32_t bbuf = 8192 + (kt & 1) * 16384;

        if (kt < 11) {
            // issue B(kt+1) + LDG A(kt+1)
            const unsigned char* wb = g_w1b + (size_t)(kt + 1) * 64 * 256;
            unsigned char* bd = smem + 8192 + ((kt + 1) & 1) * 16384;
#pragma unroll
            for (int i = 0; i < 4; i++) {
                int c = tid + 256 * i;
                int row = c >> 4, nc = c & 15;
                int csw = (nc & 8) | ((nc ^ row) & 7);
                cp_async16(bd + row * 256 + csw * 16,
                           wb + (size_t)row * 256 + nc * 16);
            }
            asm volatile("cp.async.commit_group;" ::: "memory");
            pv0 = *(const float4*)(xr + (kt + 1) * 64);
            pv1 = *(const float4*)(xr + (kt + 1) * 64 + 4);
        }

        // compute kt
#pragma unroll
        for (int ks = 0; ks < 4; ks++) {
            uint32_t a0, a1, a2, a3;
            {
                int chunk = ks * 2 + bhi;
                int csw = (chunk ^ ar7) & 7;
                ldsm_x4(a0, a1, a2, a3, sbase + abuf + arow * 128 + csw * 16);
            }
            int brow = ks * 16 + brow16;
            uint32_t braddr = sbase + bbuf + brow * 256;
            int br7 = brow & 7;
#pragma unroll
            for (int ntp = 0; ntp < 2; ntp++) {
                uint32_t b0, b1r, b2, b3;
                int chunk = nv * 4 + ntp * 2 + bhi;
                int csw = (chunk & 8) | ((chunk ^ br7) & 7);
                ldsm_x4t(b0, b1r, b2, b3, braddr + csw * 16);
                mma_bf16(d[2 * ntp],     a0, a1, a2, a3, b0, b1r);
                mma_bf16(d[2 * ntp + 1], a0, a1, a2, a3, b2, b3);
            }
        }

        if (kt < 11) {
            // STS A(kt+1) into the other buffer
            uint4 p;
            p.x = packbf2(pv0.x, pv0.y); p.y = packbf2(pv0.z, pv0.w);
            p.z = packbf2(pv1.x, pv1.y); p.w = packbf2(pv1.z, pv1.w);
            *(uint4*)(smem + (((kt + 1) & 1) * 4096) + As_row * 128 + As_csw * 16) = p;
            asm volatile("cp.async.wait_group 0;" ::: "memory");
            __syncthreads();
        }
    }
    __syncthreads();   // all warps done with A/B smem

    // ---- acc(+b1) -> h tile in smem (reuse A/B region) ----
    float* h_s = (float*)smem;                    // 32 x 133 (17024 B)
    float* rq_s = (float*)(smem + 17408);         // [64][36]  (9216 B)
    float* rk_s = (float*)(smem + 26624);         // [64][36]  (9216 B)
    {
        int r = mw * 16 + (lane >> 2);
#pragma unroll
        for (int nt = 0; nt < 4; nt++) {
            int col = nv * 32 + nt * 8 + 2 * (lane & 3);
            h_s[r * 133 + col]           = d[nt][0] + b1s[col];
            h_s[r * 133 + col + 1]       = d[nt][1] + b1s[col + 1];
            h_s[(r + 8) * 133 + col]     = d[nt][2] + b1s[col];
            h_s[(r + 8) * 133 + col + 1] = d[nt][3] + b1s[col + 1];
        }
    }
    __syncthreads();

    // ---- RoPE -> smem rope tiles ----
    const int tn = tid & 31;
    const int tmw = tid >> 5;
    const int b = row0 >> 10;
    const int s0 = row0 & 1023;
    const float invfe = invf_s[(2 * tn) & 31];
    const float invfo = invf_s[(2 * tn + 1) & 31];

#pragma unroll
    for (int mi = 0; mi < 4; mi++) {
        int r = 4 * tmw + mi;
        float h0 = h_s[r * 133 + 4 * tn + 0];
        float h1 = h_s[r * 133 + 4 * tn + 1];
        float h2 = h_s[r * 133 + 4 * tn + 2];
        float h3 = h_s[r * 133 + 4 * tn + 3];

        float fs = (float)(s0 + r);
        float se, ce, so, co;
        sincosf(fs * invfe, &se, &ce);
        sincosf(fs * invfo, &so, &co);

        rq_s[(2 * tn) * 36 + r]     = (h0 * ce - h2 * se) * 0.125f;
        rq_s[(2 * tn + 1) * 36 + r] = (h2 * co + h0 * so) * 0.125f;
        rk_s[(2 * tn) * 36 + r]     = h1 * ce - h3 * se;
        rk_s[(2 * tn + 1) * 36 + r] = h3 * co + h1 * so;
    }
    __syncthreads();

    // ---- coalesced qT/kT writeback: thread -> row d = tid>>2, 8 floats ----
    {
        int dd = tid >> 2, ch = tid & 3;
        float4 v0 = *(const float4*)&rq_s[dd * 36 + ch * 8];
        float4 v1 = *(const float4*)&rq_s[dd * 36 + ch * 8 + 4];
        float* dst = g_qT + (size_t)(b * 64 + dd) * 1024 + s0 + ch * 8;
        *(float4*)dst = v0;
        *(float4*)(dst + 4) = v1;
        float4 w0 = *(const float4*)&rk_s[dd * 36 + ch * 8];
        float4 w1 = *(const float4*)&rk_s[dd * 36 + ch * 8 + 4];
        float* dstk = g_kT + (size_t)(b * 64 + dd) * 1024 + s0 + ch * 8;
        *(float4*)dstk = w0;
        *(float4*)(dstk + 4) = w1;
    }

    // ---- bias GEMM: h @ W2 + b2 ----
    {
        const int r = tid & 31;
        const int hb4 = (tid >> 5) * 4;
        float4 accb = *(const float4*)(b2 + hb4);
        const float* hp = h_s + r * 133;
#pragma unroll 8
        for (int kk = 0; kk < 128; kk++) {
            float hv = hp[kk];
            float4 wv = *(const float4*)(W2 + kk * 32 + hb4);
            accb.x += hv * wv.x;
            accb.y += hv * wv.y;
            accb.z += hv * wv.z;
            accb.w += hv * wv.w;
        }
        int s = s0 + r;
        float vals[4] = {accb.x * 0.5f, accb.y * 0.5f, accb.z * 0.5f, accb.w * 0.5f};
#pragma unroll
        for (int j = 0; j < 4; j++) {
            int ho = hb4 + j;
            int o = ho >> 1;
            if (ho & 1) g_bB[(size_t)(b * 16 + o) * 1024 + s] = vals[j];
            else        g_bA[(size_t)(b * 16 + o) * 1024 + s] = vals[j];
        }
    }
}

// ---------------- kernel 2: logits (R8 shape, cp.async staging) -------------
__global__ __launch_bounds__(256) void k2_kernel(const float* __restrict__ mask,
                                                 float* __restrict__ out) {
    __shared__ __align__(16) float q_s[64 * 32];    // [k][m]   8KB
    __shared__ __align__(16) float k_s[64 * 128];   // [k][n]  32KB
    __shared__ __align__(16) float bA_s[16 * 128];  // [o][n]   8KB
    __shared__ __align__(16) float bB_s[16 * 32];   // [o][m]   2KB

    const int tid = threadIdx.x;
    const int tn = tid & 31;
    const int tm = tid >> 5;
    const int b = blockIdx.z;
    const int m0 = blockIdx.y * 32;
    const int n0 = blockIdx.x * 128;

    // ---- stage all tiles via cp.async (no dest registers, deep MLP) ----
    {
        const float* srcq = g_qT + (size_t)b * 65536 + m0;
#pragma unroll
        for (int i = 0; i < 2; i++) {
            int f = tid + 256 * i;
            int kk = f >> 3, col = (f & 7) * 4;
            cp_async16(&q_s[kk * 32 + col], srcq + kk * 1024 + col);
        }
        const float* srck = g_kT + (size_t)b * 65536 + n0;
#pragma unroll
        for (int i = 0; i < 8; i++) {
            int f = tid + 256 * i;
            int kk = f >> 5, col = (f & 31) * 4;
            cp_async16(&k_s[kk * 128 + col], srck + kk * 1024 + col);
        }
        const float* bAg = g_bA + (size_t)(b * 16) * 1024 + n0;
#pragma unroll
        for (int i = 0; i < 2; i++) {
            int f = tid + 256 * i;
            int o = f >> 5, col = (f & 31) * 4;
            cp_async16(&bA_s[o * 128 + col], bAg + o * 1024 + col);
        }
        if (tid < 128) {
            const float* bBg = g_bB + (size_t)(b * 16) * 1024 + m0;
            int o = tid >> 3, col = (tid & 7) * 4;
            cp_async16(&bB_s[o * 32 + col], bBg + o * 1024 + col);
        }
        asm volatile("cp.async.commit_group;" ::: "memory");
        asm volatile("cp.async.wait_group 0;" ::: "memory");
        __syncthreads();
    }

    unsigned long long acc2[4][2];
#pragma unroll
    for (int mi = 0; mi < 4; mi++) { acc2[mi][0] = 0ULL; acc2[mi][1] = 0ULL; }

#pragma unroll 16
    for (int kk = 0; kk < 64; kk++) {
        float4 av = *(const float4*)&q_s[kk * 32 + 4 * tm];
        ulonglong2 bv = *(const ulonglong2*)&k_s[kk * 128 + 4 * tn];
        unsigned long long am;
        am = pk2(av.x, av.x); fma2(acc2[0][0], am, bv.x); fma2(acc2[0][1], am, bv.y);
        am = pk2(av.y, av.y); fma2(acc2[1][0], am, bv.x); fma2(acc2[1][1], am, bv.y);
        am = pk2(av.z, av.z); fma2(acc2[2][0], am, bv.x); fma2(acc2[2][1], am, bv.y);
        am = pk2(av.w, av.w); fma2(acc2[3][0], am, bv.x); fma2(acc2[3][1], am, bv.y);
    }

    const int nbase = n0 + 4 * tn;
    const int mbase = m0 + 4 * tm;

    float pm[4];
    {
        float4 mv = *(const float4*)(mask + b * 1024 + nbase);
        pm[0] = mv.x; pm[1] = mv.y; pm[2] = mv.z; pm[3] = mv.w;
    }
    unsigned long long pm2[2] = {pk2(pm[0], pm[1]), pk2(pm[2], pm[3])};

    unsigned long long dpm2[4][2];
#pragma unroll
    for (int mi = 0; mi < 4; mi++) {
        float2 u0 = up2(acc2[mi][0]);
        float2 u1 = up2(acc2[mi][1]);
        int mg = mbase + mi;
        float c0 = -(1.0f - pm[0]) * NEGV - (mg > nbase + 0 ? NEGV : 0.0f);
        float c1 = -(1.0f - pm[1]) * NEGV - (mg > nbase + 1 ? NEGV : 0.0f);
        float c2 = -(1.0f - pm[2]) * NEGV - (mg > nbase + 2 ? NEGV : 0.0f);
        float c3 = -(1.0f - pm[3]) * NEGV - (mg > nbase + 3 ? NEGV : 0.0f);
        dpm2[mi][0] = pk2(fmaf(u0.x, pm[0], c0), fmaf(u0.y, pm[1], c1));
        dpm2[mi][1] = pk2(fmaf(u1.x, pm[2], c2), fmaf(u1.y, pm[3], c3));
    }

    float* op0 = out + ((size_t)(b * 16) * 1024 + mbase) * 1024 + nbase;

#pragma unroll 4
    for (int o = 0; o < 16; o++) {
        float4 ba = *(const float4*)&bA_s[o * 128 + 4 * tn];
        float4 bb = *(const float4*)&bB_s[o * 32 + 4 * tm];
        unsigned long long ba2[2] = {pk2(ba.x, ba.y), pk2(ba.z, ba.w)};
        float bbv[4] = {bb.x, bb.y, bb.z, bb.w};
        float* op = op0 + (size_t)o * 1024 * 1024;
#pragma unroll
        for (int mi = 0; mi < 4; mi++) {
            unsigned long long bb2 = pk2(bbv[mi], bbv[mi]);
            unsigned long long v0 = fma2n(add2(ba2[0], bb2), pm2[0], dpm2[mi][0]);
            unsigned long long v1 = fma2n(add2(ba2[1], bb2), pm2[1], dpm2[mi][1]);
            float2 r0 = up2(v0);
            float2 r1 = up2(v1);
            float4 r = make_float4(r0.x, r0.y, r1.x, r1.y);
            __stcs((float4*)(op + (size_t)mi * 1024), r);
        }
    }
}

extern "C" void kernel_launch(void* const* d_in, const int* in_sizes, int n_in,
                              void* d_out, int out_size) {
    const float* x    = (const float*)d_in[0];  // (4,1024,768)
    const float* mask = (const float*)d_in[1];  // (4,1024)
    const float* W1   = (const float*)d_in[2];  // (768,128)
    const float* b1   = (const float*)d_in[3];  // (128)
    const float* W2   = (const float*)d_in[4];  // (128,32)
    const float* b2   = (const float*)d_in[5];  // (32)
    float* out = (float*)d_out;                 // (4,16,1024,1024)

    prep_w1_kernel<<<96, 256>>>(W1);
    k1_kernel<<<128, 256>>>(x, b1, W2, b2);
    k2_kernel<<<dim3(8, 32, 4), 256>>>(mask, out);
}

// round 15
// speedup vs baseline: 1.2108x; 1.0952x over previous
#include <cuda_runtime.h>
#include <cuda_bf16.h>
#include <cstdint>
#include <math.h>

#define NEGV 1000000000000.0f

// ---------------- scratch (static device globals; no allocs) ----------------
__device__ __align__(16) unsigned char g_w1b[768 * 128 * 2];  // W1 bf16 row-major
__device__ __align__(16) unsigned char g_qb[4 * 1024 * 64 * 2]; // q bf16 [b][m][d], pre-scaled 1/8
__device__ __align__(16) unsigned char g_kb[4 * 64 * 1024 * 2]; // k bf16 [b][d][n]
__device__ float g_bA[4 * 16 * 1024];    // bias[b, n, 2o]/2   -> indexed [b][o][n]
__device__ float g_bB[4 * 16 * 1024];    // bias[b, m, 2o+1]/2 -> indexed [b][o][m]

// ---------------- packed f32x2 helpers ----------------
__device__ __forceinline__ unsigned long long pk2(float lo, float hi) {
    unsigned long long r;
    asm("mov.b64 %0, {%1,%2};" : "=l"(r) : "f"(lo), "f"(hi));
    return r;
}
__device__ __forceinline__ unsigned long long fma2n(unsigned long long a,
                                                    unsigned long long b,
                                                    unsigned long long c) {
    unsigned long long d;
    asm("fma.rn.f32x2 %0, %1, %2, %3;" : "=l"(d) : "l"(a), "l"(b), "l"(c));
    return d;
}
__device__ __forceinline__ unsigned long long add2(unsigned long long a,
                                                   unsigned long long b) {
    unsigned long long d;
    asm("add.rn.f32x2 %0, %1, %2;" : "=l"(d) : "l"(a), "l"(b));
    return d;
}
__device__ __forceinline__ float2 up2(unsigned long long v) {
    float2 r;
    asm("mov.b64 {%0,%1}, %2;" : "=f"(r.x), "=f"(r.y) : "l"(v));
    return r;
}
__device__ __forceinline__ void cp_async16(void* smem_dst, const void* gsrc) {
    unsigned saddr = (unsigned)__cvta_generic_to_shared(smem_dst);
    asm volatile("cp.async.ca.shared.global [%0], [%1], 16;\n"
                 :: "r"(saddr), "l"(gsrc) : "memory");
}
__device__ __forceinline__ uint32_t packbf2(float a, float b) {
    __nv_bfloat162 v = __floats2bfloat162_rn(a, b);
    return *(uint32_t*)&v;
}
__device__ __forceinline__ void ldsm_x4(uint32_t& r0, uint32_t& r1, uint32_t& r2,
                                        uint32_t& r3, uint32_t addr) {
    asm volatile("ldmatrix.sync.aligned.m8n8.x4.shared.b16 {%0,%1,%2,%3}, [%4];"
                 : "=r"(r0), "=r"(r1), "=r"(r2), "=r"(r3) : "r"(addr));
}
__device__ __forceinline__ void ldsm_x4t(uint32_t& r0, uint32_t& r1, uint32_t& r2,
                                         uint32_t& r3, uint32_t addr) {
    asm volatile("ldmatrix.sync.aligned.m8n8.x4.trans.shared.b16 {%0,%1,%2,%3}, [%4];"
                 : "=r"(r0), "=r"(r1), "=r"(r2), "=r"(r3) : "r"(addr));
}
__device__ __forceinline__ void mma_bf16(float* d, uint32_t a0, uint32_t a1,
                                         uint32_t a2, uint32_t a3, uint32_t b0,
                                         uint32_t b1) {
    asm volatile(
        "mma.sync.aligned.m16n8k16.row.col.f32.bf16.bf16.f32 "
        "{%0,%1,%2,%3}, {%4,%5,%6,%7}, {%8,%9}, {%0,%1,%2,%3};"
        : "+f"(d[0]), "+f"(d[1]), "+f"(d[2]), "+f"(d[3])
        : "r"(a0), "r"(a1), "r"(a2), "r"(a3), "r"(b0), "r"(b1));
}

// ---------------- prep: W1 -> bf16 row-major ----------------
__global__ __launch_bounds__(256) void prep_w1_kernel(const float* __restrict__ W1) {
    int i = (blockIdx.x * 256 + threadIdx.x) * 4;   // 98304 elements
    float4 v = *(const float4*)(W1 + i);
    uint2 p;
    p.x = packbf2(v.x, v.y);
    p.y = packbf2(v.z, v.w);
    *(uint2*)(g_w1b + (size_t)i * 2) = p;
}

// ---------------- kernel 1 (fused): h = x@W1+b1 -> RoPE (bf16) + bias -------
// 128 blocks (32 rows), 256 thr (8 warps). Full K=768 in 12 double-buffered
// BK=64 stages; B via cp.async from g_w1b, A via LDG->bf16-pack->STS.
// smem: A bufs @0 (2x4KB), B bufs @8192 (2x16KB), b1s @40960, invf @41472.
// epilogue reuse: h_s (32x133) @0, rk_s [64][36] @17408.
__global__ __launch_bounds__(256) void k1_kernel(
    const float* __restrict__ x, const float* __restrict__ b1,
    const float* __restrict__ W2, const float* __restrict__ b2) {
    __shared__ __align__(16) unsigned char smem[41600];
    const uint32_t sbase = (uint32_t)__cvta_generic_to_shared(smem);
    float* b1s = (float*)(smem + 40960);
    float* invf_s = (float*)(smem + 41472);

    const int tid = threadIdx.x;
    const int lane = tid & 31;
    const int warp = tid >> 5;
    const int row0 = blockIdx.x * 32;

    if (tid < 128) b1s[tid] = b1[tid];
    else if (tid < 160) {
        int j = tid - 128;
        invf_s[j] = (float)exp(-(double)j * (9.210340371976184 / 32.0));
    }

    // A staging map: thread -> one 16B chunk (8 bf16) of the 32x64 tile
    const int As_row = tid >> 3;       // 0..31
    const int As_kc = tid & 7;         // 0..7
    const int As_csw = (As_kc ^ (As_row & 7)) & 7;
    const float* xr = x + (size_t)(row0 + As_row) * 768 + As_kc * 8;

    // ---- prologue: stage kt=0 ----
    {
#pragma unroll
        for (int i = 0; i < 4; i++) {
            int c = tid + 256 * i;             // 1024 chunks
            int row = c >> 4, nc = c & 15;
            int csw = (nc & 8) | ((nc ^ row) & 7);
            cp_async16(smem + 8192 + row * 256 + csw * 16,
                       g_w1b + (size_t)row * 256 + nc * 16);
        }
        asm volatile("cp.async.commit_group;" ::: "memory");
        float4 v0 = *(const float4*)xr;
        float4 v1 = *(const float4*)(xr + 4);
        uint4 p;
        p.x = packbf2(v0.x, v0.y); p.y = packbf2(v0.z, v0.w);
        p.z = packbf2(v1.x, v1.y); p.w = packbf2(v1.z, v1.w);
        *(uint4*)(smem + As_row * 128 + As_csw * 16) = p;
        asm volatile("cp.async.wait_group 0;" ::: "memory");
        __syncthreads();
    }

    const int mw = warp & 1;           // m16 tile
    const int nv = warp >> 1;          // n32 group (0..3)
    const int arow = mw * 16 + (lane & 15);
    const int ar7 = arow & 7;
    const int brow16 = lane & 15;
    const int bhi = lane >> 4;

    float d[4][4];
#pragma unroll
    for (int t = 0; t < 4; t++)
#pragma unroll
        for (int j = 0; j < 4; j++) d[t][j] = 0.0f;

    float4 pv0, pv1;
    for (int kt = 0; kt < 12; kt++) {
        const uint32_t abuf = (kt & 1) * 4096;
        const uint32_t bbuf = 8192 + (kt & 1) * 16384;

        if (kt < 11) {
            const unsigned char* wb = g_w1b + (size_t)(kt + 1) * 64 * 256;
            unsigned char* bd = smem + 8192 + ((kt + 1) & 1) * 16384;
#pragma unroll
            for (int i = 0; i < 4; i++) {
                int c = tid + 256 * i;
                int row = c >> 4, nc = c & 15;
                int csw = (nc & 8) | ((nc ^ row) & 7);
                cp_async16(bd + row * 256 + csw * 16,
                           wb + (size_t)row * 256 + nc * 16);
            }
            asm volatile("cp.async.commit_group;" ::: "memory");
            pv0 = *(const float4*)(xr + (kt + 1) * 64);
            pv1 = *(const float4*)(xr + (kt + 1) * 64 + 4);
        }

#pragma unroll
        for (int ks = 0; ks < 4; ks++) {
            uint32_t a0, a1, a2, a3;
            {
                int chunk = ks * 2 + bhi;
                int csw = (chunk ^ ar7) & 7;
                ldsm_x4(a0, a1, a2, a3, sbase + abuf + arow * 128 + csw * 16);
            }
            int brow = ks * 16 + brow16;
            uint32_t braddr = sbase + bbuf + brow * 256;
            int br7 = brow & 7;
#pragma unroll
            for (int ntp = 0; ntp < 2; ntp++) {
                uint32_t b0, b1r, b2, b3;
                int chunk = nv * 4 + ntp * 2 + bhi;
                int csw = (chunk & 8) | ((chunk ^ br7) & 7);
                ldsm_x4t(b0, b1r, b2, b3, braddr + csw * 16);
                mma_bf16(d[2 * ntp],     a0, a1, a2, a3, b0, b1r);
                mma_bf16(d[2 * ntp + 1], a0, a1, a2, a3, b2, b3);
            }
        }

        if (kt < 11) {
            uint4 p;
            p.x = packbf2(pv0.x, pv0.y); p.y = packbf2(pv0.z, pv0.w);
            p.z = packbf2(pv1.x, pv1.y); p.w = packbf2(pv1.z, pv1.w);
            *(uint4*)(smem + (((kt + 1) & 1) * 4096) + As_row * 128 + As_csw * 16) = p;
            asm volatile("cp.async.wait_group 0;" ::: "memory");
            __syncthreads();
        }
    }
    __syncthreads();   // all warps done with A/B smem

    // ---- acc(+b1) -> h tile in smem (reuse A/B region) ----
    float* h_s = (float*)smem;                    // 32 x 133 (17024 B)
    float* rk_s = (float*)(smem + 17408);         // [64][36]  (9216 B)
    {
        int r = mw * 16 + (lane >> 2);
#pragma unroll
        for (int nt = 0; nt < 4; nt++) {
            int col = nv * 32 + nt * 8 + 2 * (lane & 3);
            h_s[r * 133 + col]           = d[nt][0] + b1s[col];
            h_s[r * 133 + col + 1]       = d[nt][1] + b1s[col + 1];
            h_s[(r + 8) * 133 + col]     = d[nt][2] + b1s[col];
            h_s[(r + 8) * 133 + col + 1] = d[nt][3] + b1s[col + 1];
        }
    }
    __syncthreads();

    // ---- RoPE: q -> g_qb direct (coalesced bf16 pairs), k -> rk_s tile ----
    const int tn = tid & 31;
    const int tmw = tid >> 5;
    const int b = row0 >> 10;
    const int s0 = row0 & 1023;
    const float invfe = invf_s[(2 * tn) & 31];
    const float invfo = invf_s[(2 * tn + 1) & 31];
    uint32_t* qb32 = (uint32_t*)g_qb + (size_t)b * 1024 * 32;

#pragma unroll
    for (int mi = 0; mi < 4; mi++) {
        int r = 4 * tmw + mi;
        float h0 = h_s[r * 133 + 4 * tn + 0];
        float h1 = h_s[r * 133 + 4 * tn + 1];
        float h2 = h_s[r * 133 + 4 * tn + 2];
        float h3 = h_s[r * 133 + 4 * tn + 3];

        float fs = (float)(s0 + r);
        float se, ce, so, co;
        sincosf(fs * invfe, &se, &ce);
        sincosf(fs * invfo, &so, &co);

        float qe = (h0 * ce - h2 * se) * 0.125f;   // fold 1/sqrt(64) into q
        float qo = (h2 * co + h0 * so) * 0.125f;
        qb32[(size_t)(s0 + r) * 32 + tn] = packbf2(qe, qo);
        rk_s[(2 * tn) * 36 + r]     = h1 * ce - h3 * se;
        rk_s[(2 * tn + 1) * 36 + r] = h3 * co + h1 * so;
    }
    __syncthreads();

    // ---- coalesced k writeback: thread -> dim dd = tid>>2, 8 bf16 ----
    {
        int dd = tid >> 2, ch = tid & 3;
        const float* src = &rk_s[dd * 36 + ch * 8];
        uint4 p;
        p.x = packbf2(src[0], src[1]);
        p.y = packbf2(src[2], src[3]);
        p.z = packbf2(src[4], src[5]);
        p.w = packbf2(src[6], src[7]);
        *(uint4*)(g_kb + (((size_t)(b * 64 + dd)) * 1024 + s0 + ch * 8) * 2) = p;
    }

    // ---- bias GEMM: h @ W2 + b2 ----
    {
        const int r = tid & 31;
        const int hb4 = (tid >> 5) * 4;
        float4 accb = *(const float4*)(b2 + hb4);
        const float* hp = h_s + r * 133;
#pragma unroll 8
        for (int kk = 0; kk < 128; kk++) {
            float hv = hp[kk];
            float4 wv = *(const float4*)(W2 + kk * 32 + hb4);
            accb.x += hv * wv.x;
            accb.y += hv * wv.y;
            accb.z += hv * wv.z;
            accb.w += hv * wv.w;
        }
        int s = s0 + r;
        float vals[4] = {accb.x * 0.5f, accb.y * 0.5f, accb.z * 0.5f, accb.w * 0.5f};
#pragma unroll
        for (int j = 0; j < 4; j++) {
            int ho = hb4 + j;
            int o = ho >> 1;
            if (ho & 1) g_bB[(size_t)(b * 16 + o) * 1024 + s] = vals[j];
            else        g_bA[(size_t)(b * 16 + o) * 1024 + s] = vals[j];
        }
    }
}

// ---------------- kernel 2: logits via mma.sync dots -------------------------
// smem (30720B): q_s bf16 32x128B @0 (4KB), k_s bf16 64x256B @4096 (16KB),
//   bA_s @20480 (8KB), bB_s @28672 (2KB). d_s fp32 32x132 overlays q_s/k_s.
__global__ __launch_bounds__(256) void k2_kernel(const float* __restrict__ mask,
                                                 float* __restrict__ out) {
    __shared__ __align__(16) unsigned char smem[30720];
    const uint32_t sbase = (uint32_t)__cvta_generic_to_shared(smem);
    float* bA_s = (float*)(smem + 20480);
    float* bB_s = (float*)(smem + 28672);

    const int tid = threadIdx.x;
    const int lane = tid & 31;
    const int warp = tid >> 5;
    const int tn = tid & 31;
    const int tm = tid >> 5;
    const int b = blockIdx.z;
    const int m0 = blockIdx.y * 32;
    const int n0 = blockIdx.x * 128;

    // ---- stage all tiles via cp.async ----
    {
        // q: 256 chunks (32 rows x 8), swizzled like k1 A
        int row = tid >> 3, nc = tid & 7;
        int csw = (nc ^ (row & 7)) & 7;
        cp_async16(smem + row * 128 + csw * 16,
                   g_qb + ((size_t)(b * 1024 + m0 + row) * 64) * 2 + nc * 16);
        // k: 1024 chunks (64 d-rows x 16), swizzled like k1 B
#pragma unroll
        for (int i = 0; i < 4; i++) {
            int c = tid + 256 * i;
            int krow = c >> 4, knc = c & 15;
            int kcsw = (knc & 8) | ((knc ^ krow) & 7);
            cp_async16(smem + 4096 + krow * 256 + kcsw * 16,
                       g_kb + ((size_t)(b * 64 + krow) * 1024 + n0) * 2 + knc * 16);
        }
        const float* bAg = g_bA + (size_t)(b * 16) * 1024 + n0;
#pragma unroll
        for (int i = 0; i < 2; i++) {
            int f = tid + 256 * i;
            int o = f >> 5, col = (f & 31) * 4;
            cp_async16(&bA_s[o * 128 + col], bAg + o * 1024 + col);
        }
        if (tid < 128) {
            const float* bBg = g_bB + (size_t)(b * 16) * 1024 + m0;
            int o = tid >> 3, col = (tid & 7) * 4;
            cp_async16(&bB_s[o * 32 + col], bBg + o * 1024 + col);
        }
        asm volatile("cp.async.commit_group;" ::: "memory");
        asm volatile("cp.async.wait_group 0;" ::: "memory");
        __syncthreads();
    }

    // ---- dot via mma.sync (clone of k1 mainloop, K=64 single stage) ----
    const int mw = warp & 1;           // m16 tile
    const int nv = warp >> 1;          // n32 group (0..3)
    const int arow = mw * 16 + (lane & 15);
    const int ar7 = arow & 7;
    const int brow16 = lane & 15;
    const int bhi = lane >> 4;

    float d[4][4];
#pragma unroll
    for (int t = 0; t < 4; t++)
#pragma unroll
        for (int j = 0; j < 4; j++) d[t][j] = 0.0f;

#pragma unroll
    for (int ks = 0; ks < 4; ks++) {
        uint32_t a0, a1, a2, a3;
        {
            int chunk = ks * 2 + bhi;
            int csw = (chunk ^ ar7) & 7;
            ldsm_x4(a0, a1, a2, a3, sbase + arow * 128 + csw * 16);
        }
        int brow = ks * 16 + brow16;
        uint32_t braddr = sbase + 4096 + brow * 256;
        int br7 = brow & 7;
#pragma unroll
        for (int ntp = 0; ntp < 2; ntp++) {
            uint32_t b0, b1r, b2, b3;
            int chunk = nv * 4 + ntp * 2 + bhi;
            int csw = (chunk & 8) | ((chunk ^ br7) & 7);
            ldsm_x4t(b0, b1r, b2, b3, braddr + csw * 16);
            mma_bf16(d[2 * ntp],     a0, a1, a2, a3, b0, b1r);
            mma_bf16(d[2 * ntp + 1], a0, a1, a2, a3, b2, b3);
        }
    }
    __syncthreads();   // done reading q_s/k_s

    // ---- dots -> d_s (overlay) in [m][n] layout ----
    float* d_s = (float*)smem;          // 32 x 132 fp32 (16896 B)
    {
        int r0 = mw * 16 + (lane >> 2);
        int c0 = 2 * (lane & 3);
#pragma unroll
        for (int nt = 0; nt < 4; nt++) {
            int col = nv * 32 + nt * 8 + c0;
            *(float2*)&d_s[r0 * 132 + col] = make_float2(d[nt][0], d[nt][1]);
            *(float2*)&d_s[(r0 + 8) * 132 + col] = make_float2(d[nt][2], d[nt][3]);
        }
    }
    __syncthreads();

    const int nbase = n0 + 4 * tn;
    const int mbase = m0 + 4 * tm;

    float d0[4][4];
#pragma unroll
    for (int mi = 0; mi < 4; mi++) {
        float4 v = *(const float4*)&d_s[(4 * tm + mi) * 132 + 4 * tn];
        d0[mi][0] = v.x; d0[mi][1] = v.y; d0[mi][2] = v.z; d0[mi][3] = v.w;
    }

    float pm[4];
    {
        float4 mv = *(const float4*)(mask + b * 1024 + nbase);
        pm[0] = mv.x; pm[1] = mv.y; pm[2] = mv.z; pm[3] = mv.w;
    }
    unsigned long long pm2[2] = {pk2(pm[0], pm[1]), pk2(pm[2], pm[3])};

    unsigned long long dpm2[4][2];
#pragma unroll
    for (int mi = 0; mi < 4; mi++) {
        int mg = mbase + mi;
        float c0 = -(1.0f - pm[0]) * NEGV - (mg > nbase + 0 ? NEGV : 0.0f);
        float c1 = -(1.0f - pm[1]) * NEGV - (mg > nbase + 1 ? NEGV : 0.0f);
        float c2 = -(1.0f - pm[2]) * NEGV - (mg > nbase + 2 ? NEGV : 0.0f);
        float c3 = -(1.0f - pm[3]) * NEGV - (mg > nbase + 3 ? NEGV : 0.0f);
        dpm2[mi][0] = pk2(fmaf(d0[mi][0], pm[0], c0), fmaf(d0[mi][1], pm[1], c1));
        dpm2[mi][1] = pk2(fmaf(d0[mi][2], pm[2], c2), fmaf(d0[mi][3], pm[3], c3));
    }

    float* op0 = out + ((size_t)(b * 16) * 1024 + mbase) * 1024 + nbase;

#pragma unroll 4
    for (int o = 0; o < 16; o++) {
        float4 ba = *(const float4*)&bA_s[o * 128 + 4 * tn];
        float4 bb = *(const float4*)&bB_s[o * 32 + 4 * tm];
        unsigned long long ba2[2] = {pk2(ba.x, ba.y), pk2(ba.z, ba.w)};
        float bbv[4] = {bb.x, bb.y, bb.z, bb.w};
        float* op = op0 + (size_t)o * 1024 * 1024;
#pragma unroll
        for (int mi = 0; mi < 4; mi++) {
            unsigned long long bb2 = pk2(bbv[mi], bbv[mi]);
            unsigned long long v0 = fma2n(add2(ba2[0], bb2), pm2[0], dpm2[mi][0]);
            unsigned long long v1 = fma2n(add2(ba2[1], bb2), pm2[1], dpm2[mi][1]);
            float2 r0 = up2(v0);
            float2 r1 = up2(v1);
            float4 r = make_float4(r0.x, r0.y, r1.x, r1.y);
            __stcs((float4*)(op + (size_t)mi * 1024), r);
        }
    }
}

extern "C" void kernel_launch(void* const* d_in, const int* in_sizes, int n_in,
                              void* d_out, int out_size) {
    const float* x    = (const float*)d_in[0];  // (4,1024,768)
    const float* mask = (const float*)d_in[1];  // (4,1024)
    const float* W1   = (const float*)d_in[2];  // (768,128)
    const float* b1   = (const float*)d_in[3];  // (128)
    const float* W2   = (const float*)d_in[4];  // (128,32)
    const float* b2   = (const float*)d_in[5];  // (32)
    float* out = (float*)d_out;                 // (4,16,1024,1024)

    prep_w1_kernel<<<96, 256>>>(W1);
    k1_kernel<<<128, 256>>>(x, b1, W2, b2);
    k2_kernel<<<dim3(8, 32, 4), 256>>>(mask, out);
}